// round 4
// baseline (speedup 1.0000x reference)
#include <cuda_runtime.h>
#include <stdint.h>

#define N_NODES 50000
#define N_EDGES 1000000
#define F_IN  64
#define F_HID 64
#define F_OUT 32

// ---------------- scratch (device globals: allocation-free rule) ----------------
__device__ __align__(16) float g_hs1[N_NODES * F_HID];   // dinv * (X @ W1)
__device__ __align__(16) float g_x2 [N_NODES * F_HID];   // relu(agg1 + b1)
__device__ __align__(16) float g_hs2[N_NODES * F_OUT];   // dinv * (x2 @ W2)
__device__ int g_cnt   [N_NODES];       // incoming-edge count (deg = cnt+1)
__device__ int g_rowptr[N_NODES + 1];
__device__ int g_cursor[N_NODES];
__device__ int g_csrsrc[N_EDGES];
__device__ int g_idx64;                 // 1 if edge_index is int64, 0 if int32

// Fetch edge endpoint: half=0 -> src row, half=1 -> dst row.
__device__ __forceinline__ int edge_idx(const void* ei, int half, int e) {
    if (g_idx64) {
        const long long* p = (const long long*)ei;
        return (int)p[half * N_EDGES + e];
    } else {
        const int* p = (const int*)ei;
        return p[half * N_EDGES + e];
    }
}

// ---------------- dtype detect ----------------
// int64 values < 50000 => every odd 32-bit word is 0. int32 random in [0,50000):
// essentially impossible that 2048 odd words are all 0.
__global__ void k_detect(const int* __restrict__ ei32) {
    __shared__ int any_nonzero;
    if (threadIdx.x == 0) any_nonzero = 0;
    __syncthreads();
    for (int i = threadIdx.x; i < 2048; i += blockDim.x)
        if (ei32[2 * i + 1] != 0) any_nonzero = 1;
    __syncthreads();
    if (threadIdx.x == 0) g_idx64 = any_nonzero ? 0 : 1;
}

// ---------------- CSR build ----------------
__global__ void k_zero() {
    int i = blockIdx.x * blockDim.x + threadIdx.x;
    if (i < N_NODES) g_cnt[i] = 0;
}

__global__ void k_hist(const void* __restrict__ ei) {
    int i = blockIdx.x * blockDim.x + threadIdx.x;
    if (i < N_EDGES) atomicAdd(&g_cnt[edge_idx(ei, 1, i)], 1);
}

// single-block exclusive scan of g_cnt -> g_rowptr (+ cursor init)
#define SCAN_T 1024
#define CHUNK  49           // 1024*49 = 50176 >= 50000
__global__ void __launch_bounds__(SCAN_T) k_scan() {
    __shared__ int s[SCAN_T];
    int t = threadIdx.x;
    int base = t * CHUNK;
    int local = 0;
    for (int i = 0; i < CHUNK; i++) {
        int idx = base + i;
        if (idx < N_NODES) local += g_cnt[idx];
    }
    s[t] = local;
    __syncthreads();
    for (int off = 1; off < SCAN_T; off <<= 1) {
        int v = (t >= off) ? s[t - off] : 0;
        __syncthreads();
        s[t] += v;
        __syncthreads();
    }
    int run = (t == 0) ? 0 : s[t - 1];
    for (int i = 0; i < CHUNK; i++) {
        int idx = base + i;
        if (idx < N_NODES) {
            g_rowptr[idx] = run;
            g_cursor[idx] = run;
            run += g_cnt[idx];
        }
    }
    if (t == SCAN_T - 1) g_rowptr[N_NODES] = run;
}

__global__ void k_permute(const void* __restrict__ ei) {
    int e = blockIdx.x * blockDim.x + threadIdx.x;
    if (e < N_EDGES) {
        int d = edge_idx(ei, 1, e);
        int s = edge_idx(ei, 0, e);
        int pos = atomicAdd(&g_cursor[d], 1);
        g_csrsrc[pos] = s;
    }
}

// ---------------- GEMM1: hs1 = dinv * (X @ W1) ----------------
// 128-row x 64-col tile, 128 threads, 8x8 micro-tile. 48KB smem exactly.
// Row stride 64 floats == 0 mod 32 banks -> k-XOR swizzle keyed on row group.
#define SWZ1(r, k) ((k) ^ ((((r) >> 3) & 3) << 3))
__global__ void __launch_bounds__(128) k_gemm1(const float* __restrict__ x,
                                               const float* __restrict__ W) {
    __shared__ float Xs[128][64];            // 32 KB (swizzled k)
    __shared__ float Ws[64][64];             // 16 KB
    int t = threadIdx.x;
    int row0 = blockIdx.x * 128;

    for (int i = t; i < 64 * 16; i += 128) { // 1024 float4 of W
        int k = i >> 4, c = (i & 15) * 4;
        *(float4*)&Ws[k][c] = *(const float4*)(W + k * 64 + c);
    }
    {
        int rl = t >> 4;                     // 0..7
        int kg = (t & 15) * 4;               // k base
        #pragma unroll
        for (int i = 0; i < 16; i++) {
            int r = rl + i * 8;
            int gr = row0 + r;
            float4 v = make_float4(0.f, 0.f, 0.f, 0.f);
            if (gr < N_NODES) v = *(const float4*)(x + gr * 64 + kg);
            *(float4*)&Xs[r][SWZ1(r, kg)] = v;   // swizzle is multiple of 8: float4 safe
        }
    }
    __syncthreads();

    int tx = t & 7, ty = t >> 3;             // 8 col-groups x 16 row-groups
    int cb = tx * 8, rb = ty * 8;
    float acc[8][8];
    #pragma unroll
    for (int i = 0; i < 8; i++)
        #pragma unroll
        for (int j = 0; j < 8; j++) acc[i][j] = 0.f;

    #pragma unroll
    for (int k = 0; k < 64; k++) {
        float wv[8];
        *(float4*)&wv[0] = *(float4*)&Ws[k][cb];
        *(float4*)&wv[4] = *(float4*)&Ws[k][cb + 4];
        float xv[8];
        #pragma unroll
        for (int i = 0; i < 8; i++) xv[i] = Xs[rb + i][SWZ1(rb + i, k)];
        #pragma unroll
        for (int i = 0; i < 8; i++)
            #pragma unroll
            for (int j = 0; j < 8; j++) acc[i][j] = fmaf(xv[i], wv[j], acc[i][j]);
    }

    #pragma unroll
    for (int i = 0; i < 8; i++) {
        int r = row0 + rb + i;
        if (r < N_NODES) {
            float s = rsqrtf((float)(g_cnt[r] + 1));
            float4 v0 = make_float4(acc[i][0] * s, acc[i][1] * s, acc[i][2] * s, acc[i][3] * s);
            float4 v1 = make_float4(acc[i][4] * s, acc[i][5] * s, acc[i][6] * s, acc[i][7] * s);
            *(float4*)(g_hs1 + r * 64 + cb)     = v0;
            *(float4*)(g_hs1 + r * 64 + cb + 4) = v1;
        }
    }
}

// ---------------- agg1: x2 = relu(dinv*(hs1[n] + sum hs1[src]) + b1) ----------------
// warp per node; 2 half-warps process even/odd edges; 16 lanes x float4 = 64 cols
__global__ void __launch_bounds__(256) k_agg1(const float* __restrict__ b1) {
    int node = blockIdx.x * 8 + (threadIdx.x >> 5);
    if (node >= N_NODES) return;
    int lane = threadIdx.x & 31;
    int half = lane >> 4;
    int cg = (lane & 15) * 4;

    int start = g_rowptr[node], end = g_rowptr[node + 1];
    float4 acc = make_float4(0.f, 0.f, 0.f, 0.f);
    if (half == 0) acc = *(const float4*)(g_hs1 + node * 64 + cg);   // self-loop
    for (int e = start + half; e < end; e += 2) {
        int s = g_csrsrc[e];
        float4 v = *(const float4*)(g_hs1 + s * 64 + cg);
        acc.x += v.x; acc.y += v.y; acc.z += v.z; acc.w += v.w;
    }
    acc.x += __shfl_xor_sync(0xffffffffu, acc.x, 16);
    acc.y += __shfl_xor_sync(0xffffffffu, acc.y, 16);
    acc.z += __shfl_xor_sync(0xffffffffu, acc.z, 16);
    acc.w += __shfl_xor_sync(0xffffffffu, acc.w, 16);
    if (half == 0) {
        float s = rsqrtf((float)(g_cnt[node] + 1));
        float4 bb = *(const float4*)(b1 + cg);
        float4 o;
        o.x = fmaxf(fmaf(acc.x, s, bb.x), 0.f);
        o.y = fmaxf(fmaf(acc.y, s, bb.y), 0.f);
        o.z = fmaxf(fmaf(acc.z, s, bb.z), 0.f);
        o.w = fmaxf(fmaf(acc.w, s, bb.w), 0.f);
        *(float4*)(g_x2 + node * 64 + cg) = o;
    }
}

// ---------------- GEMM2: hs2 = dinv * (x2 @ W2) ----------------
// 128 x 32 tile, 128 threads, 8x4 micro-tile. Pad Xs rows to 65: conflict-free.
__global__ void __launch_bounds__(128) k_gemm2(const float* __restrict__ W) {
    __shared__ float Xs[128][65];            // 33.3 KB
    __shared__ float Ws[64][32];             // 8 KB
    int t = threadIdx.x;
    int row0 = blockIdx.x * 128;

    for (int i = t; i < 64 * 8; i += 128) {  // 512 float4 of W2
        int k = i >> 3, c = (i & 7) * 4;
        *(float4*)&Ws[k][c] = *(const float4*)(W + k * 32 + c);
    }
    {
        int rl = t >> 4;
        int kg = (t & 15) * 4;
        #pragma unroll
        for (int i = 0; i < 16; i++) {
            int r = rl + i * 8;
            int gr = row0 + r;
            float4 v = make_float4(0.f, 0.f, 0.f, 0.f);
            if (gr < N_NODES) v = *(const float4*)(g_x2 + gr * 64 + kg);
            Xs[r][kg] = v.x; Xs[r][kg + 1] = v.y; Xs[r][kg + 2] = v.z; Xs[r][kg + 3] = v.w;
        }
    }
    __syncthreads();

    int tx = t & 7, ty = t >> 3;             // 8 col-groups(4) x 16 row-groups(8)
    int cb = tx * 4, rb = ty * 8;
    float acc[8][4];
    #pragma unroll
    for (int i = 0; i < 8; i++)
        #pragma unroll
        for (int j = 0; j < 4; j++) acc[i][j] = 0.f;

    #pragma unroll
    for (int k = 0; k < 64; k++) {
        float wv[4];
        *(float4*)&wv[0] = *(float4*)&Ws[k][cb];
        float xv[8];
        #pragma unroll
        for (int i = 0; i < 8; i++) xv[i] = Xs[rb + i][k];
        #pragma unroll
        for (int i = 0; i < 8; i++)
            #pragma unroll
            for (int j = 0; j < 4; j++) acc[i][j] = fmaf(xv[i], wv[j], acc[i][j]);
    }

    #pragma unroll
    for (int i = 0; i < 8; i++) {
        int r = row0 + rb + i;
        if (r < N_NODES) {
            float s = rsqrtf((float)(g_cnt[r] + 1));
            float4 v = make_float4(acc[i][0] * s, acc[i][1] * s, acc[i][2] * s, acc[i][3] * s);
            *(float4*)(g_hs2 + r * 32 + cb) = v;
        }
    }
}

// ---------------- agg2: out = dinv*(hs2[n] + sum hs2[src]) + b2 ----------------
// warp per node; 4 lane-quarters process edges e, e+1, e+2, e+3; 8 lanes x float4 = 32 cols
__global__ void __launch_bounds__(256) k_agg2(float* __restrict__ out,
                                              const float* __restrict__ b2) {
    int node = blockIdx.x * 8 + (threadIdx.x >> 5);
    if (node >= N_NODES) return;
    int lane = threadIdx.x & 31;
    int q = lane >> 3;
    int cg = (lane & 7) * 4;

    int start = g_rowptr[node], end = g_rowptr[node + 1];
    float4 acc = make_float4(0.f, 0.f, 0.f, 0.f);
    if (q == 0) acc = *(const float4*)(g_hs2 + node * 32 + cg);      // self-loop
    for (int e = start + q; e < end; e += 4) {
        int s = g_csrsrc[e];
        float4 v = *(const float4*)(g_hs2 + s * 32 + cg);
        acc.x += v.x; acc.y += v.y; acc.z += v.z; acc.w += v.w;
    }
    #pragma unroll
    for (int off = 8; off <= 16; off <<= 1) {
        acc.x += __shfl_xor_sync(0xffffffffu, acc.x, off);
        acc.y += __shfl_xor_sync(0xffffffffu, acc.y, off);
        acc.z += __shfl_xor_sync(0xffffffffu, acc.z, off);
        acc.w += __shfl_xor_sync(0xffffffffu, acc.w, off);
    }
    if (q == 0) {
        float s = rsqrtf((float)(g_cnt[node] + 1));
        float4 bb = *(const float4*)(b2 + cg);
        float4 o = make_float4(fmaf(acc.x, s, bb.x), fmaf(acc.y, s, bb.y),
                               fmaf(acc.z, s, bb.z), fmaf(acc.w, s, bb.w));
        *(float4*)(out + node * 32 + cg) = o;
    }
}

// ----------------------------------------------------------------
extern "C" void kernel_launch(void* const* d_in, const int* in_sizes, int n_in,
                              void* d_out, int out_size) {
    const float* x  = (const float*)d_in[0];
    const void*  ei = d_in[1];
    const float* W1 = (const float*)d_in[2];
    const float* b1 = (const float*)d_in[3];
    const float* W2 = (const float*)d_in[4];
    const float* b2 = (const float*)d_in[5];

    k_detect <<<1, 256>>>((const int*)ei);
    k_zero   <<<(N_NODES + 255) / 256, 256>>>();
    k_hist   <<<(N_EDGES + 255) / 256, 256>>>(ei);
    k_scan   <<<1, SCAN_T>>>();
    k_permute<<<(N_EDGES + 255) / 256, 256>>>(ei);
    k_gemm1  <<<(N_NODES + 127) / 128, 128>>>(x, W1);
    k_agg1   <<<(N_NODES + 7) / 8, 256>>>(b1);
    k_gemm2  <<<(N_NODES + 127) / 128, 128>>>(W2);
    k_agg2   <<<(N_NODES + 7) / 8, 256>>>((float*)d_out, b2);
}

// round 5
// speedup vs baseline: 1.7683x; 1.7683x over previous
#include <cuda_runtime.h>
#include <stdint.h>

#define N_NODES 50000
#define N_EDGES 1000000
#define F_IN  64
#define F_HID 64
#define F_OUT 32

#define SCAN_B 256
#define SCAN_NBLK ((N_NODES + SCAN_B - 1) / SCAN_B)   // 196

// ---------------- scratch (device globals: allocation-free rule) ----------------
__device__ __align__(16) float g_hs1[N_NODES * F_HID];   // dinv * (X @ W1)
__device__ __align__(16) float g_x2 [N_NODES * F_HID];   // relu(agg1 + b1)
__device__ __align__(16) float g_hs2[N_NODES * F_OUT];   // dinv * (x2 @ W2)
__device__ int g_cnt   [N_NODES];       // incoming-edge count (deg = cnt+1)
__device__ int g_rowptr[N_NODES + 1];
__device__ int g_cursor[N_NODES];
__device__ int g_csrsrc[N_EDGES];
__device__ int g_bsum  [SCAN_NBLK];
__device__ int g_boff  [SCAN_NBLK];
__device__ int g_idx64;                 // 1 if edge_index is int64, 0 if int32

// Fetch edge endpoint: half=0 -> src row, half=1 -> dst row.
__device__ __forceinline__ int edge_idx(const void* ei, int half, int e) {
    if (g_idx64) {
        const long long* p = (const long long*)ei;
        return (int)p[half * N_EDGES + e];
    } else {
        const int* p = (const int*)ei;
        return p[half * N_EDGES + e];
    }
}

// ---------------- dtype detect ----------------
// int64 values < 50000 => every odd 32-bit word is 0. int32 random in [0,50000):
// essentially impossible that 2048 odd words are all 0.
__global__ void k_detect(const int* __restrict__ ei32) {
    __shared__ int any_nonzero;
    if (threadIdx.x == 0) any_nonzero = 0;
    __syncthreads();
    for (int i = threadIdx.x; i < 2048; i += blockDim.x)
        if (ei32[2 * i + 1] != 0) any_nonzero = 1;
    __syncthreads();
    if (threadIdx.x == 0) g_idx64 = any_nonzero ? 0 : 1;
}

// ---------------- CSR build ----------------
__global__ void k_zero() {
    int i = blockIdx.x * blockDim.x + threadIdx.x;
    if (i < N_NODES) g_cnt[i] = 0;
}

__global__ void k_hist(const void* __restrict__ ei) {
    int i = blockIdx.x * blockDim.x + threadIdx.x;
    if (i < N_EDGES) atomicAdd(&g_cnt[edge_idx(ei, 1, i)], 1);
}

// phase 1: per-block sums of g_cnt
__global__ void __launch_bounds__(SCAN_B) k_blocksums() {
    __shared__ int s[SCAN_B];
    int i = blockIdx.x * SCAN_B + threadIdx.x;
    s[threadIdx.x] = (i < N_NODES) ? g_cnt[i] : 0;
    __syncthreads();
    #pragma unroll
    for (int off = SCAN_B / 2; off > 0; off >>= 1) {
        if (threadIdx.x < off) s[threadIdx.x] += s[threadIdx.x + off];
        __syncthreads();
    }
    if (threadIdx.x == 0) g_bsum[blockIdx.x] = s[0];
}

// phase 2: exclusive scan of the 196 block sums (one tiny block)
__global__ void __launch_bounds__(SCAN_B) k_scanbsums() {
    __shared__ int s[SCAN_B];
    int t = threadIdx.x;
    s[t] = (t < SCAN_NBLK) ? g_bsum[t] : 0;
    __syncthreads();
    #pragma unroll
    for (int off = 1; off < SCAN_B; off <<= 1) {
        int v = (t >= off) ? s[t - off] : 0;
        __syncthreads();
        s[t] += v;
        __syncthreads();
    }
    if (t < SCAN_NBLK) g_boff[t] = (t == 0) ? 0 : s[t - 1];
    if (t == SCAN_NBLK - 1) g_rowptr[N_NODES] = s[t];
}

// phase 3: in-block exclusive scan + block offset -> rowptr, cursor
__global__ void __launch_bounds__(SCAN_B) k_rowptr() {
    __shared__ int s[SCAN_B];
    int t = threadIdx.x;
    int i = blockIdx.x * SCAN_B + t;
    s[t] = (i < N_NODES) ? g_cnt[i] : 0;
    __syncthreads();
    #pragma unroll
    for (int off = 1; off < SCAN_B; off <<= 1) {
        int v = (t >= off) ? s[t - off] : 0;
        __syncthreads();
        s[t] += v;
        __syncthreads();
    }
    if (i < N_NODES) {
        int excl = g_boff[blockIdx.x] + ((t == 0) ? 0 : s[t - 1]);
        g_rowptr[i] = excl;
        g_cursor[i] = excl;
    }
}

__global__ void k_permute(const void* __restrict__ ei) {
    int e = blockIdx.x * blockDim.x + threadIdx.x;
    if (e < N_EDGES) {
        int d = edge_idx(ei, 1, e);
        int s = edge_idx(ei, 0, e);
        int pos = atomicAdd(&g_cursor[d], 1);
        g_csrsrc[pos] = s;
    }
}

// ---------------- GEMM1: hs1 = dinv * (X @ W1) ----------------
// 128-row x 64-col tile, 128 threads, 8x8 micro-tile. 48KB smem exactly.
// Row stride 64 floats == 0 mod 32 banks -> k-XOR swizzle keyed on row group.
#define SWZ1(r, k) ((k) ^ ((((r) >> 3) & 3) << 3))
__global__ void __launch_bounds__(128) k_gemm1(const float* __restrict__ x,
                                               const float* __restrict__ W) {
    __shared__ float Xs[128][64];            // 32 KB (swizzled k)
    __shared__ float Ws[64][64];             // 16 KB
    int t = threadIdx.x;
    int row0 = blockIdx.x * 128;

    for (int i = t; i < 64 * 16; i += 128) { // 1024 float4 of W
        int k = i >> 4, c = (i & 15) * 4;
        *(float4*)&Ws[k][c] = *(const float4*)(W + k * 64 + c);
    }
    {
        int rl = t >> 4;                     // 0..7
        int kg = (t & 15) * 4;               // k base
        #pragma unroll
        for (int i = 0; i < 16; i++) {
            int r = rl + i * 8;
            int gr = row0 + r;
            float4 v = make_float4(0.f, 0.f, 0.f, 0.f);
            if (gr < N_NODES) v = *(const float4*)(x + gr * 64 + kg);
            *(float4*)&Xs[r][SWZ1(r, kg)] = v;   // swizzle is multiple of 8: float4 safe
        }
    }
    __syncthreads();

    int tx = t & 7, ty = t >> 3;             // 8 col-groups x 16 row-groups
    int cb = tx * 8, rb = ty * 8;
    float acc[8][8];
    #pragma unroll
    for (int i = 0; i < 8; i++)
        #pragma unroll
        for (int j = 0; j < 8; j++) acc[i][j] = 0.f;

    #pragma unroll
    for (int k = 0; k < 64; k++) {
        float wv[8];
        *(float4*)&wv[0] = *(float4*)&Ws[k][cb];
        *(float4*)&wv[4] = *(float4*)&Ws[k][cb + 4];
        float xv[8];
        #pragma unroll
        for (int i = 0; i < 8; i++) xv[i] = Xs[rb + i][SWZ1(rb + i, k)];
        #pragma unroll
        for (int i = 0; i < 8; i++)
            #pragma unroll
            for (int j = 0; j < 8; j++) acc[i][j] = fmaf(xv[i], wv[j], acc[i][j]);
    }

    #pragma unroll
    for (int i = 0; i < 8; i++) {
        int r = row0 + rb + i;
        if (r < N_NODES) {
            float s = rsqrtf((float)(g_cnt[r] + 1));
            float4 v0 = make_float4(acc[i][0] * s, acc[i][1] * s, acc[i][2] * s, acc[i][3] * s);
            float4 v1 = make_float4(acc[i][4] * s, acc[i][5] * s, acc[i][6] * s, acc[i][7] * s);
            *(float4*)(g_hs1 + r * 64 + cb)     = v0;
            *(float4*)(g_hs1 + r * 64 + cb + 4) = v1;
        }
    }
}

// ---------------- agg1: x2 = relu(dinv*(hs1[n] + sum hs1[src]) + b1) ----------------
// warp per node; 2 half-warps process even/odd edges; 16 lanes x float4 = 64 cols
__global__ void __launch_bounds__(256) k_agg1(const float* __restrict__ b1) {
    int node = blockIdx.x * 8 + (threadIdx.x >> 5);
    if (node >= N_NODES) return;
    int lane = threadIdx.x & 31;
    int half = lane >> 4;
    int cg = (lane & 15) * 4;

    int start = g_rowptr[node], end = g_rowptr[node + 1];
    float4 acc = make_float4(0.f, 0.f, 0.f, 0.f);
    if (half == 0) acc = *(const float4*)(g_hs1 + node * 64 + cg);   // self-loop
    for (int e = start + half; e < end; e += 2) {
        int s = g_csrsrc[e];
        float4 v = *(const float4*)(g_hs1 + s * 64 + cg);
        acc.x += v.x; acc.y += v.y; acc.z += v.z; acc.w += v.w;
    }
    acc.x += __shfl_xor_sync(0xffffffffu, acc.x, 16);
    acc.y += __shfl_xor_sync(0xffffffffu, acc.y, 16);
    acc.z += __shfl_xor_sync(0xffffffffu, acc.z, 16);
    acc.w += __shfl_xor_sync(0xffffffffu, acc.w, 16);
    if (half == 0) {
        float s = rsqrtf((float)(g_cnt[node] + 1));
        float4 bb = *(const float4*)(b1 + cg);
        float4 o;
        o.x = fmaxf(fmaf(acc.x, s, bb.x), 0.f);
        o.y = fmaxf(fmaf(acc.y, s, bb.y), 0.f);
        o.z = fmaxf(fmaf(acc.z, s, bb.z), 0.f);
        o.w = fmaxf(fmaf(acc.w, s, bb.w), 0.f);
        *(float4*)(g_x2 + node * 64 + cg) = o;
    }
}

// ---------------- GEMM2: hs2 = dinv * (x2 @ W2) ----------------
// 128 x 32 tile, 128 threads, 8x4 micro-tile. Pad Xs rows to 65: conflict-free.
__global__ void __launch_bounds__(128) k_gemm2(const float* __restrict__ W) {
    __shared__ float Xs[128][65];            // 33.3 KB
    __shared__ float Ws[64][32];             // 8 KB
    int t = threadIdx.x;
    int row0 = blockIdx.x * 128;

    for (int i = t; i < 64 * 8; i += 128) {  // 512 float4 of W2
        int k = i >> 3, c = (i & 7) * 4;
        *(float4*)&Ws[k][c] = *(const float4*)(W + k * 32 + c);
    }
    {
        int rl = t >> 4;
        int kg = (t & 15) * 4;
        #pragma unroll
        for (int i = 0; i < 16; i++) {
            int r = rl + i * 8;
            int gr = row0 + r;
            float4 v = make_float4(0.f, 0.f, 0.f, 0.f);
            if (gr < N_NODES) v = *(const float4*)(g_x2 + gr * 64 + kg);
            Xs[r][kg] = v.x; Xs[r][kg + 1] = v.y; Xs[r][kg + 2] = v.z; Xs[r][kg + 3] = v.w;
        }
    }
    __syncthreads();

    int tx = t & 7, ty = t >> 3;             // 8 col-groups(4) x 16 row-groups(8)
    int cb = tx * 4, rb = ty * 8;
    float acc[8][4];
    #pragma unroll
    for (int i = 0; i < 8; i++)
        #pragma unroll
        for (int j = 0; j < 4; j++) acc[i][j] = 0.f;

    #pragma unroll
    for (int k = 0; k < 64; k++) {
        float wv[4];
        *(float4*)&wv[0] = *(float4*)&Ws[k][cb];
        float xv[8];
        #pragma unroll
        for (int i = 0; i < 8; i++) xv[i] = Xs[rb + i][k];
        #pragma unroll
        for (int i = 0; i < 8; i++)
            #pragma unroll
            for (int j = 0; j < 4; j++) acc[i][j] = fmaf(xv[i], wv[j], acc[i][j]);
    }

    #pragma unroll
    for (int i = 0; i < 8; i++) {
        int r = row0 + rb + i;
        if (r < N_NODES) {
            float s = rsqrtf((float)(g_cnt[r] + 1));
            float4 v = make_float4(acc[i][0] * s, acc[i][1] * s, acc[i][2] * s, acc[i][3] * s);
            *(float4*)(g_hs2 + r * 32 + cb) = v;
        }
    }
}

// ---------------- agg2: out = dinv*(hs2[n] + sum hs2[src]) + b2 ----------------
// warp per node; 4 lane-quarters process edges e, e+1, e+2, e+3; 8 lanes x float4 = 32 cols
__global__ void __launch_bounds__(256) k_agg2(float* __restrict__ out,
                                              const float* __restrict__ b2) {
    int node = blockIdx.x * 8 + (threadIdx.x >> 5);
    if (node >= N_NODES) return;
    int lane = threadIdx.x & 31;
    int q = lane >> 3;
    int cg = (lane & 7) * 4;

    int start = g_rowptr[node], end = g_rowptr[node + 1];
    float4 acc = make_float4(0.f, 0.f, 0.f, 0.f);
    if (q == 0) acc = *(const float4*)(g_hs2 + node * 32 + cg);      // self-loop
    for (int e = start + q; e < end; e += 4) {
        int s = g_csrsrc[e];
        float4 v = *(const float4*)(g_hs2 + s * 32 + cg);
        acc.x += v.x; acc.y += v.y; acc.z += v.z; acc.w += v.w;
    }
    #pragma unroll
    for (int off = 8; off <= 16; off <<= 1) {
        acc.x += __shfl_xor_sync(0xffffffffu, acc.x, off);
        acc.y += __shfl_xor_sync(0xffffffffu, acc.y, off);
        acc.z += __shfl_xor_sync(0xffffffffu, acc.z, off);
        acc.w += __shfl_xor_sync(0xffffffffu, acc.w, off);
    }
    if (q == 0) {
        float s = rsqrtf((float)(g_cnt[node] + 1));
        float4 bb = *(const float4*)(b2 + cg);
        float4 o = make_float4(fmaf(acc.x, s, bb.x), fmaf(acc.y, s, bb.y),
                               fmaf(acc.z, s, bb.z), fmaf(acc.w, s, bb.w));
        *(float4*)(out + node * 32 + cg) = o;
    }
}

// ----------------------------------------------------------------
extern "C" void kernel_launch(void* const* d_in, const int* in_sizes, int n_in,
                              void* d_out, int out_size) {
    const float* x  = (const float*)d_in[0];
    const void*  ei = d_in[1];
    const float* W1 = (const float*)d_in[2];
    const float* b1 = (const float*)d_in[3];
    const float* W2 = (const float*)d_in[4];
    const float* b2 = (const float*)d_in[5];

    k_detect    <<<1, 256>>>((const int*)ei);
    k_zero      <<<(N_NODES + 255) / 256, 256>>>();
    k_hist      <<<(N_EDGES + 255) / 256, 256>>>(ei);
    k_blocksums <<<SCAN_NBLK, SCAN_B>>>();
    k_scanbsums <<<1, SCAN_B>>>();
    k_rowptr    <<<SCAN_NBLK, SCAN_B>>>();
    k_permute   <<<(N_EDGES + 255) / 256, 256>>>(ei);
    k_gemm1     <<<(N_NODES + 127) / 128, 128>>>(x, W1);
    k_agg1      <<<(N_NODES + 7) / 8, 256>>>(b1);
    k_gemm2     <<<(N_NODES + 127) / 128, 128>>>(W2);
    k_agg2      <<<(N_NODES + 7) / 8, 256>>>((float*)d_out, b2);
}

// round 7
// speedup vs baseline: 1.8860x; 1.0666x over previous
#include <cuda_runtime.h>
#include <cuda_fp16.h>
#include <stdint.h>

#define N_NODES 50000
#define N_EDGES 1000000
#define F_IN  64
#define F_HID 64
#define F_OUT 32

#define SCAN_B 256
#define SCAN_NBLK ((N_NODES + SCAN_B - 1) / SCAN_B)   // 196

// ---------------- scratch (device globals: allocation-free rule) ----------------
__device__ __align__(16) __half g_hs1h[N_NODES * F_HID];  // fp16 dinv*(X@W1)
__device__ __align__(16) float  g_x2  [N_NODES * F_HID];  // relu(agg1 + b1), fp32
__device__ __align__(16) __half g_hs2h[N_NODES * F_OUT];  // fp16 dinv*(x2@W2)
__device__ int g_cnt   [N_NODES];       // incoming-edge count (deg = cnt+1)
__device__ int g_rowptr[N_NODES + 1];
__device__ int g_cursor[N_NODES];
__device__ int g_csrsrc[N_EDGES];
__device__ int g_bsum  [SCAN_NBLK];
__device__ int g_boff  [SCAN_NBLK];
__device__ int g_idx64;                 // 1 if edge_index is int64, 0 if int32

// Fetch edge endpoint: half=0 -> src row, half=1 -> dst row.
__device__ __forceinline__ int edge_idx(const void* ei, int half, int e) {
    if (g_idx64) {
        const long long* p = (const long long*)ei;
        return (int)p[half * N_EDGES + e];
    } else {
        const int* p = (const int*)ei;
        return p[half * N_EDGES + e];
    }
}

// ---------------- dtype detect + cnt zero (fused) ----------------
__global__ void k_detect_zero(const int* __restrict__ ei32) {
    int i = blockIdx.x * blockDim.x + threadIdx.x;
    if (i < N_NODES) g_cnt[i] = 0;
    if (blockIdx.x == 0) {
        __shared__ int any_nonzero;
        if (threadIdx.x == 0) any_nonzero = 0;
        __syncthreads();
        for (int j = threadIdx.x; j < 2048; j += blockDim.x)
            if (ei32[2 * j + 1] != 0) any_nonzero = 1;
        __syncthreads();
        if (threadIdx.x == 0) g_idx64 = any_nonzero ? 0 : 1;
    }
}

__global__ void k_hist(const void* __restrict__ ei) {
    int i = blockIdx.x * blockDim.x + threadIdx.x;
    if (i < N_EDGES) atomicAdd(&g_cnt[edge_idx(ei, 1, i)], 1);
}

// phase 1: per-block sums of g_cnt
__global__ void __launch_bounds__(SCAN_B) k_blocksums() {
    __shared__ int s[SCAN_B];
    int i = blockIdx.x * SCAN_B + threadIdx.x;
    s[threadIdx.x] = (i < N_NODES) ? g_cnt[i] : 0;
    __syncthreads();
    #pragma unroll
    for (int off = SCAN_B / 2; off > 0; off >>= 1) {
        if (threadIdx.x < off) s[threadIdx.x] += s[threadIdx.x + off];
        __syncthreads();
    }
    if (threadIdx.x == 0) g_bsum[blockIdx.x] = s[0];
}

// phase 2: exclusive scan of the 196 block sums (one tiny block)
__global__ void __launch_bounds__(SCAN_B) k_scanbsums() {
    __shared__ int s[SCAN_B];
    int t = threadIdx.x;
    s[t] = (t < SCAN_NBLK) ? g_bsum[t] : 0;
    __syncthreads();
    #pragma unroll
    for (int off = 1; off < SCAN_B; off <<= 1) {
        int v = (t >= off) ? s[t - off] : 0;
        __syncthreads();
        s[t] += v;
        __syncthreads();
    }
    if (t < SCAN_NBLK) g_boff[t] = (t == 0) ? 0 : s[t - 1];
    if (t == SCAN_NBLK - 1) g_rowptr[N_NODES] = s[t];
}

// phase 3: in-block exclusive scan + block offset -> rowptr, cursor
__global__ void __launch_bounds__(SCAN_B) k_rowptr() {
    __shared__ int s[SCAN_B];
    int t = threadIdx.x;
    int i = blockIdx.x * SCAN_B + t;
    s[t] = (i < N_NODES) ? g_cnt[i] : 0;
    __syncthreads();
    #pragma unroll
    for (int off = 1; off < SCAN_B; off <<= 1) {
        int v = (t >= off) ? s[t - off] : 0;
        __syncthreads();
        s[t] += v;
        __syncthreads();
    }
    if (i < N_NODES) {
        int excl = g_boff[blockIdx.x] + ((t == 0) ? 0 : s[t - 1]);
        g_rowptr[i] = excl;
        g_cursor[i] = excl;
    }
}

__global__ void k_permute(const void* __restrict__ ei) {
    int e = blockIdx.x * blockDim.x + threadIdx.x;
    if (e < N_EDGES) {
        int d = edge_idx(ei, 1, e);
        int s = edge_idx(ei, 0, e);
        int pos = atomicAdd(&g_cursor[d], 1);
        g_csrsrc[pos] = s;
    }
}

// ---------------- GEMM1: hs1h = fp16( dinv * (X @ W1) ) ----------------
// 128-row x 64-col tile, 128 threads, 8x8 micro-tile.
#define SWZ1(r, k) ((k) ^ ((((r) >> 3) & 3) << 3))
__global__ void __launch_bounds__(128) k_gemm1(const float* __restrict__ x,
                                               const float* __restrict__ W) {
    __shared__ float Xs[128][64];            // 32 KB (swizzled k)
    __shared__ float Ws[64][64];             // 16 KB
    int t = threadIdx.x;
    int row0 = blockIdx.x * 128;

    for (int i = t; i < 64 * 16; i += 128) { // 1024 float4 of W
        int k = i >> 4, c = (i & 15) * 4;
        *(float4*)&Ws[k][c] = *(const float4*)(W + k * 64 + c);
    }
    {
        int rl = t >> 4;                     // 0..7
        int kg = (t & 15) * 4;               // k base
        #pragma unroll
        for (int i = 0; i < 16; i++) {
            int r = rl + i * 8;
            int gr = row0 + r;
            float4 v = make_float4(0.f, 0.f, 0.f, 0.f);
            if (gr < N_NODES) v = *(const float4*)(x + gr * 64 + kg);
            *(float4*)&Xs[r][SWZ1(r, kg)] = v;
        }
    }
    __syncthreads();

    int tx = t & 7, ty = t >> 3;             // 8 col-groups x 16 row-groups
    int cb = tx * 8, rb = ty * 8;
    float acc[8][8];
    #pragma unroll
    for (int i = 0; i < 8; i++)
        #pragma unroll
        for (int j = 0; j < 8; j++) acc[i][j] = 0.f;

    #pragma unroll
    for (int k = 0; k < 64; k++) {
        float wv[8];
        *(float4*)&wv[0] = *(float4*)&Ws[k][cb];
        *(float4*)&wv[4] = *(float4*)&Ws[k][cb + 4];
        float xv[8];
        #pragma unroll
        for (int i = 0; i < 8; i++) xv[i] = Xs[rb + i][SWZ1(rb + i, k)];
        #pragma unroll
        for (int i = 0; i < 8; i++)
            #pragma unroll
            for (int j = 0; j < 8; j++) acc[i][j] = fmaf(xv[i], wv[j], acc[i][j]);
    }

    #pragma unroll
    for (int i = 0; i < 8; i++) {
        int r = row0 + rb + i;
        if (r < N_NODES) {
            float s = rsqrtf((float)(g_cnt[r] + 1));
            __half2 h[4];
            #pragma unroll
            for (int j = 0; j < 4; j++)
                h[j] = __floats2half2_rn(acc[i][2*j] * s, acc[i][2*j+1] * s);
            *(uint4*)(g_hs1h + r * 64 + cb) = *(uint4*)h;   // 8 halves = 16B
        }
    }
}

// ---------------- agg1: x2 = relu(dinv*(hs1[n] + sum hs1[src]) + b1) ----------------
// warp per node; lane l owns half2 column l (64 cols = 32 half2 = 128B row).
// No reduction needed. Edge loop unrolled x4 for MLP.
__global__ void __launch_bounds__(256) k_agg1(const float* __restrict__ b1) {
    int node = blockIdx.x * 8 + (threadIdx.x >> 5);
    if (node >= N_NODES) return;
    int lane = threadIdx.x & 31;
    const __half2* hs = (const __half2*)g_hs1h;

    int start = g_rowptr[node], end = g_rowptr[node + 1];
    float2 f = __half22float2(hs[node * 32 + lane]);        // self-loop
    float2 acc = make_float2(f.x, f.y);

    int e = start;
    for (; e + 4 <= end; e += 4) {
        int s0 = g_csrsrc[e + 0], s1 = g_csrsrc[e + 1];
        int s2 = g_csrsrc[e + 2], s3 = g_csrsrc[e + 3];
        __half2 h0 = hs[s0 * 32 + lane], h1 = hs[s1 * 32 + lane];
        __half2 h2 = hs[s2 * 32 + lane], h3 = hs[s3 * 32 + lane];
        float2 f0 = __half22float2(h0), f1 = __half22float2(h1);
        float2 f2 = __half22float2(h2), f3 = __half22float2(h3);
        acc.x += (f0.x + f1.x) + (f2.x + f3.x);
        acc.y += (f0.y + f1.y) + (f2.y + f3.y);
    }
    for (; e < end; e++) {
        float2 v = __half22float2(hs[g_csrsrc[e] * 32 + lane]);
        acc.x += v.x; acc.y += v.y;
    }

    float s = rsqrtf((float)(g_cnt[node] + 1));
    float2 bb = *(const float2*)(b1 + 2 * lane);
    float2 o;
    o.x = fmaxf(fmaf(acc.x, s, bb.x), 0.f);
    o.y = fmaxf(fmaf(acc.y, s, bb.y), 0.f);
    *(float2*)(g_x2 + node * 64 + 2 * lane) = o;
}

// ---------------- GEMM2: hs2h = fp16( dinv * (x2 @ W2) ) ----------------
__global__ void __launch_bounds__(128) k_gemm2(const float* __restrict__ W) {
    __shared__ float Xs[128][65];            // 33.3 KB
    __shared__ float Ws[64][32];             // 8 KB
    int t = threadIdx.x;
    int row0 = blockIdx.x * 128;

    for (int i = t; i < 64 * 8; i += 128) {  // 512 float4 of W2
        int k = i >> 3, c = (i & 7) * 4;
        *(float4*)&Ws[k][c] = *(const float4*)(W + k * 32 + c);
    }
    {
        int rl = t >> 4;
        int kg = (t & 15) * 4;
        #pragma unroll
        for (int i = 0; i < 16; i++) {
            int r = rl + i * 8;
            int gr = row0 + r;
            float4 v = make_float4(0.f, 0.f, 0.f, 0.f);
            if (gr < N_NODES) v = *(const float4*)(g_x2 + gr * 64 + kg);
            Xs[r][kg] = v.x; Xs[r][kg + 1] = v.y; Xs[r][kg + 2] = v.z; Xs[r][kg + 3] = v.w;
        }
    }
    __syncthreads();

    int tx = t & 7, ty = t >> 3;             // 8 col-groups(4) x 16 row-groups(8)
    int cb = tx * 4, rb = ty * 8;
    float acc[8][4];
    #pragma unroll
    for (int i = 0; i < 8; i++)
        #pragma unroll
        for (int j = 0; j < 4; j++) acc[i][j] = 0.f;

    #pragma unroll
    for (int k = 0; k < 64; k++) {
        float wv[4];
        *(float4*)&wv[0] = *(float4*)&Ws[k][cb];
        float xv[8];
        #pragma unroll
        for (int i = 0; i < 8; i++) xv[i] = Xs[rb + i][k];
        #pragma unroll
        for (int i = 0; i < 8; i++)
            #pragma unroll
            for (int j = 0; j < 4; j++) acc[i][j] = fmaf(xv[i], wv[j], acc[i][j]);
    }

    #pragma unroll
    for (int i = 0; i < 8; i++) {
        int r = row0 + rb + i;
        if (r < N_NODES) {
            float s = rsqrtf((float)(g_cnt[r] + 1));
            __half2 h[2];
            h[0] = __floats2half2_rn(acc[i][0] * s, acc[i][1] * s);
            h[1] = __floats2half2_rn(acc[i][2] * s, acc[i][3] * s);
            *(uint2*)(g_hs2h + r * 32 + cb) = *(uint2*)h;   // 4 halves = 8B
        }
    }
}

// ---------------- agg2: out = dinv*(hs2[n] + sum hs2[src]) + b2 ----------------
// warp per node; 2 sub-warps of 16 lanes alternate edges; lane owns half2 col
// (32 cols = 16 half2 = 64B row). FIX: strided pair-load bound is e+2 < end
// (previous e+2 <= end read csrsrc[end] = next node's first edge).
__global__ void __launch_bounds__(256) k_agg2(float* __restrict__ out,
                                              const float* __restrict__ b2) {
    int node = blockIdx.x * 8 + (threadIdx.x >> 5);
    if (node >= N_NODES) return;
    int lane = threadIdx.x & 31;
    int sub = lane >> 4;                     // 0/1
    int c = lane & 15;                       // half2 column
    const __half2* hs = (const __half2*)g_hs2h;

    int start = g_rowptr[node], end = g_rowptr[node + 1];
    float2 acc = make_float2(0.f, 0.f);
    if (sub == 0) {
        float2 f = __half22float2(hs[node * 16 + c]);       // self-loop
        acc.x = f.x; acc.y = f.y;
    }
    int e = start + sub;
    for (; e + 2 < end; e += 4) {            // reads e and e+2: need e+2 <= end-1
        int s0 = g_csrsrc[e], s1 = g_csrsrc[e + 2];
        float2 f0 = __half22float2(hs[s0 * 16 + c]);
        float2 f1 = __half22float2(hs[s1 * 16 + c]);
        acc.x += f0.x + f1.x; acc.y += f0.y + f1.y;
    }
    if (e < end) {
        float2 f = __half22float2(hs[g_csrsrc[e] * 16 + c]);
        acc.x += f.x; acc.y += f.y;
    }
    acc.x += __shfl_xor_sync(0xffffffffu, acc.x, 16);
    acc.y += __shfl_xor_sync(0xffffffffu, acc.y, 16);
    if (sub == 0) {
        float s = rsqrtf((float)(g_cnt[node] + 1));
        float2 bb = *(const float2*)(b2 + 2 * c);
        float2 o = make_float2(fmaf(acc.x, s, bb.x), fmaf(acc.y, s, bb.y));
        *(float2*)(out + node * 32 + 2 * c) = o;
    }
}

// ----------------------------------------------------------------
extern "C" void kernel_launch(void* const* d_in, const int* in_sizes, int n_in,
                              void* d_out, int out_size) {
    const float* x  = (const float*)d_in[0];
    const void*  ei = d_in[1];
    const float* W1 = (const float*)d_in[2];
    const float* b1 = (const float*)d_in[3];
    const float* W2 = (const float*)d_in[4];
    const float* b2 = (const float*)d_in[5];

    k_detect_zero<<<SCAN_NBLK, 256>>>((const int*)ei);
    k_hist      <<<(N_EDGES + 255) / 256, 256>>>(ei);
    k_blocksums <<<SCAN_NBLK, SCAN_B>>>();
    k_scanbsums <<<1, SCAN_B>>>();
    k_rowptr    <<<SCAN_NBLK, SCAN_B>>>();
    k_permute   <<<(N_EDGES + 255) / 256, 256>>>(ei);
    k_gemm1     <<<(N_NODES + 127) / 128, 128>>>(x, W1);
    k_agg1      <<<(N_NODES + 7) / 8, 256>>>(b1);
    k_gemm2     <<<(N_NODES + 127) / 128, 128>>>(W2);
    k_agg2      <<<(N_NODES + 7) / 8, 256>>>((float*)d_out, b2);
}